// round 2
// baseline (speedup 1.0000x reference)
#include <cuda_runtime.h>

// Conv2d: x(16,64,112,112) * w(128,64,3,3) + bias(128) -> out(16,128,112,112)
// stride 1, pad 1, cross-correlation, NCHW fp32.
// Implemented as implicit GEMM: M=128 (oc), N=200704 (n*h*w), K=576 (ic*3*3).

#define IN_C   64
#define OUT_C  128
#define HWDIM  112
#define NBATCH 16
#define HW2    (HWDIM * HWDIM)      // 12544
#define CHW    (IN_C * HW2)         // per-image x stride
#define KSZ    (IN_C * 9)           // 576
#define NPIX   (NBATCH * HW2)       // 200704

#define TILE_P 128
#define TILE_K 8

__global__ __launch_bounds__(256, 2)
void conv3x3_igemm_kernel(const float* __restrict__ x,
                          const float* __restrict__ w,
                          const float* __restrict__ bias,
                          float* __restrict__ out)
{
    __shared__ float As[2][TILE_K][OUT_C];    // [kk][oc]  weights
    __shared__ float Bs[2][TILE_K][TILE_P];   // [kk][px]  im2col gather

    const int tid = threadIdx.x;
    const int p0  = blockIdx.x * TILE_P;

    // ---- B-load assignment: each thread loads 4 k-rows of one pixel column
    const int bc  = tid & 127;            // pixel column 0..127
    const int bk0 = (tid >> 7) * 4;       // kk base: 0 or 4

    const int p    = p0 + bc;
    const int n    = p / HW2;
    const int hw   = p - n * HW2;
    const int h    = hw / HWDIM;
    const int wcol = hw - h * HWDIM;
    const long xbase = (long)n * CHW + (long)h * HWDIM + wcol;

    // ---- A-load assignment: each thread loads float4 along k for one oc
    const int aoc = tid >> 1;             // 0..127
    const int akq = (tid & 1) * 4;        // 0 or 4

    // ---- microkernel coords: 16x16 thread grid, 8 oc x 8 px per thread
    const int tx  = tid & 15;
    const int ty  = tid >> 4;
    const int oc0 = ty * 8;
    const int pc0 = tx * 8;

    float acc[8][8];
#pragma unroll
    for (int i = 0; i < 8; i++)
#pragma unroll
        for (int j = 0; j < 8; j++) acc[i][j] = 0.0f;

    // stage loader
    auto load_stage = [&](int k0, int buf) {
        // A: weight is already [OUT_C, KSZ] row-major
        float4 av = *reinterpret_cast<const float4*>(&w[(long)aoc * KSZ + k0 + akq]);
        As[buf][akq + 0][aoc] = av.x;
        As[buf][akq + 1][aoc] = av.y;
        As[buf][akq + 2][aoc] = av.z;
        As[buf][akq + 3][aoc] = av.w;
        // B: on-the-fly im2col with zero padding
#pragma unroll
        for (int j = 0; j < 4; j++) {
            const int k  = k0 + bk0 + j;
            const int ic = k / 9;
            const int r  = k - ic * 9;
            const int kh = r / 3;
            const int kw = r - kh * 3;
            const int hi = h + kh - 1;
            const int wi = wcol + kw - 1;
            float v = 0.0f;
            if ((unsigned)hi < HWDIM && (unsigned)wi < HWDIM)
                v = x[xbase + (long)ic * HW2 + (kh - 1) * HWDIM + (kw - 1)];
            Bs[buf][bk0 + j][bc] = v;
        }
    };

    load_stage(0, 0);
    __syncthreads();

    const int NTILES = KSZ / TILE_K;   // 72
    for (int t = 0; t < NTILES; t++) {
        const int buf = t & 1;
        if (t + 1 < NTILES) load_stage((t + 1) * TILE_K, buf ^ 1);

#pragma unroll
        for (int kk = 0; kk < TILE_K; kk++) {
            float a[8], b[8];
            *reinterpret_cast<float4*>(&a[0]) = *reinterpret_cast<const float4*>(&As[buf][kk][oc0]);
            *reinterpret_cast<float4*>(&a[4]) = *reinterpret_cast<const float4*>(&As[buf][kk][oc0 + 4]);
            *reinterpret_cast<float4*>(&b[0]) = *reinterpret_cast<const float4*>(&Bs[buf][kk][pc0]);
            *reinterpret_cast<float4*>(&b[4]) = *reinterpret_cast<const float4*>(&Bs[buf][kk][pc0 + 4]);
#pragma unroll
            for (int i = 0; i < 8; i++)
#pragma unroll
                for (int j = 0; j < 8; j++)
                    acc[i][j] += a[i] * b[j];
        }
        __syncthreads();
    }

    // ---- epilogue: 8 consecutive pixels per thread stay inside one image
    // (HW2 = 12544 is divisible by 8) and are 16B-aligned.
    const int pg   = p0 + pc0;
    const int ng   = pg / HW2;
    const int hwg  = pg - ng * HW2;

#pragma unroll
    for (int i = 0; i < 8; i++) {
        const int oc = oc0 + i;
        const float bv = bias[oc];
        float4 v0, v1;
        v0.x = acc[i][0] + bv; v0.y = acc[i][1] + bv;
        v0.z = acc[i][2] + bv; v0.w = acc[i][3] + bv;
        v1.x = acc[i][4] + bv; v1.y = acc[i][5] + bv;
        v1.z = acc[i][6] + bv; v1.w = acc[i][7] + bv;
        float* dst = &out[((long)ng * OUT_C + oc) * HW2 + hwg];
        *reinterpret_cast<float4*>(dst)     = v0;
        *reinterpret_cast<float4*>(dst + 4) = v1;
    }
}

extern "C" void kernel_launch(void* const* d_in, const int* in_sizes, int n_in,
                              void* d_out, int out_size)
{
    const float* x    = (const float*)d_in[0];
    const float* w    = (const float*)d_in[1];
    const float* bias = (const float*)d_in[2];
    float* out        = (float*)d_out;

    const int grid = NPIX / TILE_P;   // 1568
    conv3x3_igemm_kernel<<<grid, 256>>>(x, w, bias, out);
}

// round 4
// speedup vs baseline: 2.1454x; 2.1454x over previous
#include <cuda_runtime.h>
#include <cstdint>

// Conv2d 3x3 s1 p1, NCHW fp32: x(16,64,112,112) * w(128,64,3,3) + bias -> (16,128,112,112)
// Implicit GEMM via mma.sync.m16n8k8.tf32 (baseline PTX, legacy HMMA pipe on sm_103).
// CTA: 128 px x 128 oc, K=576 in 18 chunks of 32, double-buffered SMEM + reg staging.

#define IN_C   64
#define OUT_C  128
#define HWD    112
#define NB     16
#define HW2    (HWD * HWD)        // 12544
#define CHW    (IN_C * HW2)
#define KSZ    576
#define NPIX   (NB * HW2)         // 200704
#define BK     32
#define NCHUNK 18                 // 576/32
#define LDA    36                 // padded k-stride (floats): (4g+t)%32 distinct -> conflict-free

#define SMEM_FLOATS (4 * 128 * LDA)      // A0,B0,A1,B1
#define SMEM_BYTES  (SMEM_FLOATS * 4)    // 73728

__device__ __forceinline__ uint32_t f2tf32(float f) {
    uint32_t u;
    asm("cvt.rna.tf32.f32 %0, %1;" : "=r"(u) : "f"(f));
    return u;
}

__device__ __forceinline__ void mma_tf32(float c[4], const uint32_t a[4], const uint32_t b[2]) {
    asm volatile(
        "mma.sync.aligned.m16n8k8.row.col.f32.tf32.tf32.f32 "
        "{%0,%1,%2,%3}, {%4,%5,%6,%7}, {%8,%9}, {%0,%1,%2,%3};"
        : "+f"(c[0]), "+f"(c[1]), "+f"(c[2]), "+f"(c[3])
        : "r"(a[0]), "r"(a[1]), "r"(a[2]), "r"(a[3]), "r"(b[0]), "r"(b[1]));
}

__global__ void __launch_bounds__(256)
conv3x3_mma_tf32(const float* __restrict__ x,
                 const float* __restrict__ w,
                 const float* __restrict__ bias,
                 float* __restrict__ out)
{
    extern __shared__ float sm[];
    float* const Abuf[2] = { sm,               sm + 2 * 128 * LDA };
    float* const Bbuf[2] = { sm + 128 * LDA,   sm + 3 * 128 * LDA };

    const int tid  = threadIdx.x;
    const int wid  = tid >> 5;
    const int lane = tid & 31;
    const int p0   = blockIdx.x * 128;

    // ---------------- im2col gather state (A = activations) ----------------
    // warp wid owns k-columns [wid*4, wid*4+4); pixel rows it*32+lane, it=0..3
    const int kcb = wid * 4;
    int xb[4], hh[4], ww[4];
#pragma unroll
    for (int it = 0; it < 4; it++) {
        const int p  = p0 + it * 32 + lane;
        const int n  = p / HW2;
        const int hw = p - n * HW2;
        const int h  = hw / HWD;
        const int wc = hw - h * HWD;
        hh[it] = h; ww[it] = wc;
        xb[it] = n * CHW + (h - 1) * HWD + (wc - 1);   // tap (kh=0,kw=0) base
    }
    int ic[4], kh[4], kw[4];
#pragma unroll
    for (int j = 0; j < 4; j++) {
        const int k = kcb + j;
        ic[j] = k / 9;
        const int r = k - ic[j] * 9;
        kh[j] = r / 3; kw[j] = r - kh[j] * 3;
    }

    auto gatherA = [&](float v[4][4]) {
#pragma unroll
        for (int it = 0; it < 4; it++) {
            const int h = hh[it], wc = ww[it];
#pragma unroll
            for (int j = 0; j < 4; j++) {
                const bool ok = ((unsigned)(h + kh[j] - 1) < HWD) &
                                ((unsigned)(wc + kw[j] - 1) < HWD);
                v[it][j] = ok ? __ldg(x + xb[it] + ic[j] * HW2 + kh[j] * HWD + kw[j]) : 0.0f;
            }
        }
    };
    auto advA = [&]() {    // k += 32  <=>  r += 5 (mod 9), ic += 3 or 4
#pragma unroll
        for (int j = 0; j < 4; j++) {
            int r = kh[j] * 3 + kw[j] + 5;
            int add = 3;
            if (r >= 9) { r -= 9; add = 4; }
            ic[j] += add;
            kh[j] = r / 3; kw[j] = r - kh[j] * 3;
        }
    };
    auto storeA = [&](float* A, float v[4][4]) {
#pragma unroll
        for (int it = 0; it < 4; it++) {
            uint4 u;
            u.x = f2tf32(v[it][0]); u.y = f2tf32(v[it][1]);
            u.z = f2tf32(v[it][2]); u.w = f2tf32(v[it][3]);
            *reinterpret_cast<uint4*>(&A[(it * 32 + lane) * LDA + kcb]) = u;
        }
    };

    // ---------------- weight loads (B) ----------------
    auto gatherB = [&](int k0, float4 v[4]) {
#pragma unroll
        for (int i = 0; i < 4; i++) {
            const int f   = tid + 256 * i;
            const int row = f >> 3;
            const int q   = f & 7;
            v[i] = *reinterpret_cast<const float4*>(w + row * KSZ + k0 + q * 4);
        }
    };
    auto storeB = [&](float* B, float4 v[4]) {
#pragma unroll
        for (int i = 0; i < 4; i++) {
            const int f   = tid + 256 * i;
            const int row = f >> 3;
            const int q   = f & 7;
            uint4 u;
            u.x = f2tf32(v[i].x); u.y = f2tf32(v[i].y);
            u.z = f2tf32(v[i].z); u.w = f2tf32(v[i].w);
            *reinterpret_cast<uint4*>(&B[row * LDA + q * 4]) = u;
        }
    };

    // ---------------- microkernel ----------------
    const int wm = wid >> 1;   // 0..3 : px tile of 32
    const int wn = wid & 1;    // 0..1 : oc tile of 64
    const int g  = lane >> 2;
    const int t  = lane & 3;

    float acc[2][8][4];
#pragma unroll
    for (int i = 0; i < 2; i++)
#pragma unroll
        for (int j = 0; j < 8; j++)
#pragma unroll
            for (int c = 0; c < 4; c++) acc[i][j][c] = 0.0f;

    auto compute = [&](const float* A, const float* B) {
        const uint32_t* Au = reinterpret_cast<const uint32_t*>(A);
        const uint32_t* Bu = reinterpret_cast<const uint32_t*>(B);
#pragma unroll
        for (int kk = 0; kk < 4; kk++) {
            const int k0 = kk * 8;
            uint32_t a[2][4];
#pragma unroll
            for (int i = 0; i < 2; i++) {
                const int rm = wm * 32 + i * 16 + g;
                a[i][0] = Au[rm * LDA + k0 + t];
                a[i][1] = Au[(rm + 8) * LDA + k0 + t];
                a[i][2] = Au[rm * LDA + k0 + t + 4];
                a[i][3] = Au[(rm + 8) * LDA + k0 + t + 4];
            }
#pragma unroll
            for (int j = 0; j < 8; j++) {
                const int nr = wn * 64 + j * 8 + g;
                uint32_t b[2];
                b[0] = Bu[nr * LDA + k0 + t];
                b[1] = Bu[nr * LDA + k0 + t + 4];
                mma_tf32(acc[0][j], a[0], b);
                mma_tf32(acc[1][j], a[1], b);
            }
        }
    };

    // ---------------- mainloop: double-buffered, reg-staged ----------------
    float av[4][4];
    float4 bv[4];

    gatherA(av); gatherB(0, bv);
    storeA(Abuf[0], av); storeB(Bbuf[0], bv);
    advA();
    __syncthreads();

    for (int tch = 0; tch < NCHUNK; tch++) {
        const int buf = tch & 1;
        if (tch + 1 < NCHUNK) { gatherA(av); gatherB((tch + 1) * BK, bv); }
        compute(Abuf[buf], Bbuf[buf]);
        if (tch + 1 < NCHUNK) {
            storeA(Abuf[buf ^ 1], av); storeB(Bbuf[buf ^ 1], bv);
            advA();
        }
        __syncthreads();
    }

    // ---------------- epilogue ----------------
    // CTA's 128 px are within one image (HW2 % 128 == 0).
    const int n   = p0 / HW2;
    const int hw0 = p0 - n * HW2;
    float* const ob = out + (size_t)n * OUT_C * HW2 + hw0;

#pragma unroll
    for (int j = 0; j < 8; j++) {
        const int oc0 = wn * 64 + j * 8 + 2 * t;
        const float bv0 = __ldg(bias + oc0);
        const float bv1 = __ldg(bias + oc0 + 1);
        float* const c0 = ob + (size_t)oc0 * HW2;
        float* const c1 = ob + (size_t)(oc0 + 1) * HW2;
#pragma unroll
        for (int i = 0; i < 2; i++) {
            const int pr = wm * 32 + i * 16 + g;
            c0[pr]     = acc[i][j][0] + bv0;
            c1[pr]     = acc[i][j][1] + bv1;
            c0[pr + 8] = acc[i][j][2] + bv0;
            c1[pr + 8] = acc[i][j][3] + bv1;
        }
    }
}

extern "C" void kernel_launch(void* const* d_in, const int* in_sizes, int n_in,
                              void* d_out, int out_size)
{
    const float* x    = (const float*)d_in[0];
    const float* w    = (const float*)d_in[1];
    const float* bias = (const float*)d_in[2];
    float* out        = (float*)d_out;

    cudaFuncSetAttribute(conv3x3_mma_tf32,
                         cudaFuncAttributeMaxDynamicSharedMemorySize, SMEM_BYTES);
    conv3x3_mma_tf32<<<NPIX / 128, 256, SMEM_BYTES>>>(x, w, bias, out);
}

// round 6
// speedup vs baseline: 3.6631x; 1.7074x over previous
#include <cuda_runtime.h>
#include <cstdint>

// Conv2d 3x3 s1 p1, NCHW fp32 -> implicit GEMM, mma.sync.m16n8k8.tf32.
// K reordered as k' = tap*64 + ic  (fixed tap per BK=32 chunk).
// 3-stage cp.async pipeline, tiles [k][px]/[k][oc] with pad 136, 2 CTAs/SM.

#define IN_C   64
#define OUT_C  128
#define HWD    112
#define NB     16
#define HW2    (HWD * HWD)        // 12544
#define CHW    (IN_C * HW2)
#define KSZ    576
#define NPIX   (NB * HW2)         // 200704
#define XELEMS (NB * CHW)         // 12845056
#define BK     32
#define NCHUNK 18
#define LDP    136                // padded px/oc stride (floats)
#define STG    (BK * LDP)         // 4352 floats per tile
#define NSTAGE 3
#define SMEM_BYTES (NSTAGE * 2 * STG * 4)   // 104448

__device__ float g_xr[XELEMS];          // rna(tf32)-rounded x
__device__ float g_wt[KSZ * OUT_C];     // rounded + reordered weights [k'][oc]

__device__ __forceinline__ uint32_t f2tf32(float f) {
    uint32_t u;
    asm("cvt.rna.tf32.f32 %0, %1;" : "=r"(u) : "f"(f));
    return u;
}

__global__ void __launch_bounds__(256)
prep_x(const float* __restrict__ x) {
    const int i = (blockIdx.x * 256 + threadIdx.x) * 4;
    float4 v = *reinterpret_cast<const float4*>(x + i);
    uint4 u;
    u.x = f2tf32(v.x); u.y = f2tf32(v.y); u.z = f2tf32(v.z); u.w = f2tf32(v.w);
    *reinterpret_cast<uint4*>(g_xr + i) = u;
}

__global__ void __launch_bounds__(256)
prep_w(const float* __restrict__ w) {
    const int idx = blockIdx.x * 256 + threadIdx.x;  // 73728 = 576*128
    const int kp  = idx >> 7;       // k' = tap*64 + ic
    const int oc  = idx & 127;
    const int tap = kp >> 6;
    const int ic  = kp & 63;
    g_wt[idx] = __uint_as_float(f2tf32(w[oc * KSZ + ic * 9 + tap]));
}

__device__ __forceinline__ void mma_tf32(float c[4], const uint32_t a[4], const uint32_t b[2]) {
    asm volatile(
        "mma.sync.aligned.m16n8k8.row.col.f32.tf32.tf32.f32 "
        "{%0,%1,%2,%3}, {%4,%5,%6,%7}, {%8,%9}, {%0,%1,%2,%3};"
        : "+f"(c[0]), "+f"(c[1]), "+f"(c[2]), "+f"(c[3])
        : "r"(a[0]), "r"(a[1]), "r"(a[2]), "r"(a[3]), "r"(b[0]), "r"(b[1]));
}

__global__ void __launch_bounds__(256, 2)
conv_main(const float* __restrict__ bias, float* __restrict__ out)
{
    extern __shared__ float sm[];
    const int tid  = threadIdx.x;
    const int wid  = tid >> 5;
    const int lane = tid & 31;
    const int p0   = blockIdx.x * 128;

    uint32_t sbase;
    asm("{ .reg .u64 t; cvta.to.shared.u64 t, %1; cvt.u32.u64 %0, t; }" : "=r"(sbase) : "l"(sm));

    // ---------- A gather setup: lanes -> consecutive pixels ----------
    const int pxl  = tid & 127;           // pixel column within tile
    const int kh16 = (tid >> 7) * 16;     // this thread's 16 k-rows base
    const int p    = p0 + pxl;
    const int n    = p / HW2;
    const int hw   = p - n * HW2;
    const int h    = hw / HWD;
    const int wc   = hw - h * HWD;
    const long xb0 = (long)n * CHW + h * HWD + wc;
    // per-tap validity bitmasks
    const int hok = ((h > 0) ? 1 : 0) | 2 | ((h < HWD - 1) ? 4 : 0);
    const int wok = ((wc > 0) ? 1 : 0) | 2 | ((wc < HWD - 1) ? 4 : 0);

    // ---------- microkernel coords ----------
    const int wm = wid >> 1;   // px subtile (32)
    const int wn = wid & 1;    // oc subtile (64)
    const int g  = lane >> 2;
    const int tq = lane & 3;

    float acc[2][8][4];
#pragma unroll
    for (int i = 0; i < 2; i++)
#pragma unroll
        for (int j = 0; j < 8; j++)
#pragma unroll
            for (int c = 0; c < 4; c++) acc[i][j][c] = 0.0f;

    auto issue = [&](int t) {
        const int stage = t % NSTAGE;
        const uint32_t aoff = sbase + stage * (2 * STG * 4);
        const uint32_t boff = aoff + STG * 4;
        // --- A: 16x 4B cp.async with zero-fill predication
        const int tap = t >> 1;
        const int kh  = (tap * 11) >> 5;       // tap/3
        const int kw  = tap - kh * 3;
        const int ic0 = (t & 1) * 32 + kh16;
        const bool ok = ((hok >> kh) & 1) && ((wok >> kw) & 1);
        const uint32_t szr = ok ? 4u : 0u;
        const float* src = ok ? (g_xr + xb0 + (kh - 1) * HWD + (kw - 1) + (long)ic0 * HW2)
                              : g_xr;
        const long sstep = ok ? (long)HW2 : 0;
        uint32_t d = aoff + (uint32_t)(kh16 * LDP + pxl) * 4u;
#pragma unroll
        for (int j = 0; j < 16; j++) {
            asm volatile("cp.async.ca.shared.global [%0], [%1], 4, %2;"
                         :: "r"(d), "l"(src), "r"(szr) : "memory");
            d += LDP * 4;
            src += sstep;
        }
        // --- B: 4x 16B cp.async, [k][oc]
        const int k0 = t * BK;
#pragma unroll
        for (int i = 0; i < 4; i++) {
            const int f   = tid + 256 * i;
            const int kr  = f >> 5;
            const int ocq = (f & 31) * 4;
            const float* s2 = g_wt + (size_t)(k0 + kr) * OUT_C + ocq;
            const uint32_t d2 = boff + (uint32_t)(kr * LDP + ocq) * 4u;
            asm volatile("cp.async.cg.shared.global [%0], [%1], 16;"
                         :: "r"(d2), "l"(s2) : "memory");
        }
    };

    auto compute = [&](const float* As, const float* Bs) {
        const uint32_t* Au = reinterpret_cast<const uint32_t*>(As);
        const uint32_t* Bu = reinterpret_cast<const uint32_t*>(Bs);
#pragma unroll
        for (int kk = 0; kk < 4; kk++) {
            const int k0 = kk * 8;
            uint32_t a[2][4];
#pragma unroll
            for (int i = 0; i < 2; i++) {
                const int rm = wm * 32 + i * 16 + g;
                a[i][0] = Au[(k0 + tq) * LDP + rm];
                a[i][1] = Au[(k0 + tq) * LDP + rm + 8];
                a[i][2] = Au[(k0 + tq + 4) * LDP + rm];
                a[i][3] = Au[(k0 + tq + 4) * LDP + rm + 8];
            }
#pragma unroll
            for (int j = 0; j < 8; j++) {
                const int nr = wn * 64 + j * 8 + g;
                uint32_t b[2];
                b[0] = Bu[(k0 + tq) * LDP + nr];
                b[1] = Bu[(k0 + tq + 4) * LDP + nr];
                mma_tf32(acc[0][j], a[0], b);
                mma_tf32(acc[1][j], a[1], b);
            }
        }
    };

    // ---------- pipeline ----------
    issue(0);
    asm volatile("cp.async.commit_group;" ::: "memory");
    issue(1);
    asm volatile("cp.async.commit_group;" ::: "memory");

    for (int t = 0; t < NCHUNK; t++) {
        asm volatile("cp.async.wait_group 1;" ::: "memory");
        __syncthreads();
        const float* As = sm + (t % NSTAGE) * (2 * STG);
        compute(As, As + STG);
        __syncthreads();
        if (t + 2 < NCHUNK) issue(t + 2);
        asm volatile("cp.async.commit_group;" ::: "memory");
    }

    // ---------- epilogue (same mapping as R4) ----------
    const int n2  = p0 / HW2;
    const int hw0 = p0 - n2 * HW2;
    float* const ob = out + (size_t)n2 * OUT_C * HW2 + hw0;

#pragma unroll
    for (int j = 0; j < 8; j++) {
        const int oc0 = wn * 64 + j * 8 + 2 * tq;
        const float bv0 = __ldg(bias + oc0);
        const float bv1 = __ldg(bias + oc0 + 1);
        float* const c0 = ob + (size_t)oc0 * HW2;
        float* const c1 = ob + (size_t)(oc0 + 1) * HW2;
#pragma unroll
        for (int i = 0; i < 2; i++) {
            const int pr = wm * 32 + i * 16 + g;
            c0[pr]     = acc[i][j][0] + bv0;
            c1[pr]     = acc[i][j][1] + bv1;
            c0[pr + 8] = acc[i][j][2] + bv0;
            c1[pr + 8] = acc[i][j][3] + bv1;
        }
    }
}

extern "C" void kernel_launch(void* const* d_in, const int* in_sizes, int n_in,
                              void* d_out, int out_size)
{
    const float* x    = (const float*)d_in[0];
    const float* w    = (const float*)d_in[1];
    const float* bias = (const float*)d_in[2];
    float* out        = (float*)d_out;

    prep_x<<<XELEMS / 1024, 256>>>(x);        // 12544 blocks
    prep_w<<<(KSZ * OUT_C) / 256, 256>>>(w);  // 288 blocks

    cudaFuncSetAttribute(conv_main,
                         cudaFuncAttributeMaxDynamicSharedMemorySize, SMEM_BYTES);
    conv_main<<<NPIX / 128, 256, SMEM_BYTES>>>(bias, out);
}

// round 7
// speedup vs baseline: 5.3589x; 1.4629x over previous
#include <cuda_runtime.h>
#include <cuda_fp16.h>
#include <cstdint>

// Conv2d 3x3 s1 p1, NCHW fp32 -> implicit GEMM, mma.sync.m16n8k16.f16 (f32 accum).
// K reordered k' = tap*64 + ic (fixed tap per BK=32 chunk). Activations pre-converted
// to fp16 into 3 kw-shifted, h-padded copies -> mainloop has ZERO predication and
// all-aligned 16B cp.async. Pixel tile = 8h x 16w (128 px) x 128 oc per CTA.

#define IN_C   64
#define OUT_C  128
#define HWD    112
#define NB     16
#define HW2    (HWD * HWD)          // 12544
#define KSZ    576
#define BK     32
#define NCHUNK 18
#define LDH    136                  // padded halves per k-row (272 B)
#define TILE_HB (BK * LDH * 2)      // 8704 B per A or B tile
#define STAGE_BYTES (2 * TILE_HB)   // 17408
#define NSTAGE 4
#define SMEM_BYTES (NSTAGE * STAGE_BYTES)   // 69632

#define XS_PLANE   (114 * 112)              // 12768 halves per (ic) plane
#define XS_COPY    (NB * IN_C * XS_PLANE)   // halves per kw copy
#define XS_TOTAL   (3 * XS_COPY)            // 39,223,296 halves (~78 MB)

__device__ __half g_xs[XS_TOTAL];        // [kw][n][ic][h'=114][w=112], zero borders
__device__ __half g_wh[KSZ * OUT_C];     // [k'][oc], k' = tap*64+ic

// ---------------- prep kernels ----------------
__global__ void __launch_bounds__(256)
prep_xs(const float* __restrict__ x) {
    const int idx = blockIdx.x * 256 + threadIdx.x;    // 4,902,912 total
    const int w8  = idx % 14;
    int r  = idx / 14;
    const int hp  = r % 114;  r /= 114;
    const int ic  = r & 63;   r >>= 6;
    const int n   = r & 15;
    const int kw  = r >> 4;

    const int h_in = hp - 1;
    const bool hv  = (unsigned)h_in < HWD;
    const float* xr = x + ((size_t)(n * IN_C + ic) * HWD + h_in) * HWD;

    __half hs[8];
#pragma unroll
    for (int j = 0; j < 8; j++) {
        const int w_in = w8 * 8 + j + kw - 1;
        float v = (hv && (unsigned)w_in < HWD) ? __ldg(xr + w_in) : 0.0f;
        hs[j] = __float2half_rn(v);
    }
    __half* dst = g_xs + ((size_t)(kw * NB + n) * IN_C + ic) * XS_PLANE
                       + hp * HWD + w8 * 8;
    *reinterpret_cast<uint4*>(dst) = *reinterpret_cast<const uint4*>(hs);
}

__global__ void __launch_bounds__(256)
prep_wh(const float* __restrict__ w) {
    const int idx = blockIdx.x * 256 + threadIdx.x;    // 73728
    const int kp  = idx >> 7;
    const int oc  = idx & 127;
    const int tap = kp >> 6;
    const int ic  = kp & 63;
    g_wh[idx] = __float2half_rn(w[oc * KSZ + ic * 9 + tap]);
}

// ---------------- main kernel ----------------
__device__ __forceinline__ void mma_f16(float c[4], const uint32_t a[4],
                                        uint32_t b0, uint32_t b1) {
    asm volatile(
        "mma.sync.aligned.m16n8k16.row.col.f32.f16.f16.f32 "
        "{%0,%1,%2,%3}, {%4,%5,%6,%7}, {%8,%9}, {%0,%1,%2,%3};"
        : "+f"(c[0]), "+f"(c[1]), "+f"(c[2]), "+f"(c[3])
        : "r"(a[0]), "r"(a[1]), "r"(a[2]), "r"(a[3]), "r"(b0), "r"(b1));
}

#define LDSM_T(r0, r1, r2, r3, addr)                                          \
    asm volatile("ldmatrix.sync.aligned.m8n8.x4.trans.shared.b16 "            \
                 "{%0,%1,%2,%3}, [%4];"                                       \
                 : "=r"(r0), "=r"(r1), "=r"(r2), "=r"(r3) : "r"(addr))

__global__ void __launch_bounds__(256, 2)
conv_main(const float* __restrict__ bias, float* __restrict__ out)
{
    extern __shared__ __align__(16) char smc[];
    uint32_t sbase;
    asm("{ .reg .u64 t; cvta.to.shared.u64 t, %1; cvt.u32.u64 %0, t; }"
        : "=r"(sbase) : "l"(smc));

    const int tid  = threadIdx.x;
    const int wid  = tid >> 5;
    const int lane = tid & 31;

    const int b   = blockIdx.x;          // 1568 = 16 images * 98 tiles
    const int n   = b / 98;
    const int rem = b - n * 98;
    const int th  = rem / 7;
    const int tw  = rem - th * 7;
    const int h0  = th * 8;
    const int w0  = tw * 16;

    // ---- A-load constants (2 segments of 16B per thread) ----
    const char* const xsb = reinterpret_cast<const char*>(g_xs);
    long  srcA[2];
    uint32_t dstA[2];
#pragma unroll
    for (int s = 0; s < 2; s++) {
        const int seg  = tid + s * 256;        // 0..511
        const int ic   = seg >> 4;             // 0..31
        const int rr   = (seg >> 1) & 7;
        const int hf   = seg & 1;
        srcA[s] = ((long)(n * IN_C + ic) * 114 + h0 + rr) * 224 + w0 * 2 + hf * 16;
        dstA[s] = (uint32_t)(ic * LDH + rr * 16 + hf * 8) * 2;
    }
    // ---- B-load constants ----
    const char* const whb = reinterpret_cast<const char*>(g_wh);
    long  srcB[2];
    uint32_t dstB[2];
#pragma unroll
    for (int s = 0; s < 2; s++) {
        const int seg = tid + s * 256;
        const int kr  = seg >> 4;
        const int ocq = (seg & 15) * 8;
        srcB[s] = (long)(kr * OUT_C + ocq) * 2;
        dstB[s] = (uint32_t)(kr * LDH + ocq) * 2;
    }

    auto issue = [&](int t) {
        const int stage = t & 3;               // NSTAGE = 4
        const uint32_t abase = sbase + stage * STAGE_BYTES;
        const uint32_t bbase = abase + TILE_HB;
        const int tap = t >> 1;
        const int kh  = (tap >= 3) ? ((tap >= 6) ? 2 : 1) : 0;
        const int kw  = tap - kh * 3;
        const long aoff = (long)kw * (XS_COPY * 2)       // kw copy
                        + (long)((t & 1) * 32) * 25536   // ic0 * 114*224
                        + (long)kh * 224;                // h' shift
#pragma unroll
        for (int s = 0; s < 2; s++)
            asm volatile("cp.async.cg.shared.global [%0], [%1], 16;"
                         :: "r"(abase + dstA[s]), "l"(xsb + srcA[s] + aoff) : "memory");
        const long boff = (long)t * BK * OUT_C * 2;
#pragma unroll
        for (int s = 0; s < 2; s++)
            asm volatile("cp.async.cg.shared.global [%0], [%1], 16;"
                         :: "r"(bbase + dstB[s]), "l"(whb + srcB[s] + boff) : "memory");
    };

    // ---- microkernel coords ----
    const int wm = wid >> 1;     // px subtile of 32 (rows wm*2, wm*2+1)
    const int wn = wid & 1;      // oc subtile of 64
    // ldmatrix lane offsets (halves)
    const uint32_t aoffL = (uint32_t)(((lane >> 4) * 8 + (lane & 7)) * LDH
                                      + wm * 32 + ((lane >> 3) & 1) * 8);
    const uint32_t boffL = (uint32_t)(((((lane >> 3) & 1) * 8) + (lane & 7)) * LDH
                                      + wn * 64 + (lane >> 4) * 8);

    float acc[2][4][2][4];
#pragma unroll
    for (int i = 0; i < 2; i++)
#pragma unroll
        for (int j = 0; j < 4; j++)
#pragma unroll
            for (int h = 0; h < 2; h++)
#pragma unroll
                for (int c = 0; c < 4; c++) acc[i][j][h][c] = 0.0f;

    auto compute = [&](int stage) {
        const uint32_t abase = sbase + stage * STAGE_BYTES;
        const uint32_t bbase = abase + TILE_HB;
#pragma unroll
        for (int kk2 = 0; kk2 < 2; kk2++) {
            const uint32_t kof = kk2 * 16 * LDH;
            uint32_t a[2][4];
#pragma unroll
            for (int i = 0; i < 2; i++)
                LDSM_T(a[i][0], a[i][1], a[i][2], a[i][3],
                       abase + (aoffL + kof + i * 16) * 2);
#pragma unroll
            for (int j2 = 0; j2 < 4; j2++) {
                uint32_t b0, b1, b2, b3;
                LDSM_T(b0, b1, b2, b3, bbase + (boffL + kof + j2 * 16) * 2);
                mma_f16(acc[0][j2][0], a[0], b0, b1);
                mma_f16(acc[1][j2][0], a[1], b0, b1);
                mma_f16(acc[0][j2][1], a[0], b2, b3);
                mma_f16(acc[1][j2][1], a[1], b2, b3);
            }
        }
    };

    // ---- pipeline ----
    issue(0); asm volatile("cp.async.commit_group;" ::: "memory");
    issue(1); asm volatile("cp.async.commit_group;" ::: "memory");
    issue(2); asm volatile("cp.async.commit_group;" ::: "memory");

    for (int t = 0; t < NCHUNK; t++) {
        asm volatile("cp.async.wait_group 2;" ::: "memory");
        __syncthreads();
        compute(t & 3);
        if (t + 3 < NCHUNK) issue(t + 3);
        asm volatile("cp.async.commit_group;" ::: "memory");
    }

    // ---- epilogue: C frag (m=g -> w-col, n=2t -> oc pair) ----
    const int g  = lane >> 2;
    const int t4 = lane & 3;
#pragma unroll
    for (int i = 0; i < 2; i++) {
        const int rr = wm * 2 + i;                       // local h row
        float* const rowp = out + (size_t)n * OUT_C * HW2 + (h0 + rr) * HWD + w0;
#pragma unroll
        for (int j2 = 0; j2 < 4; j2++)
#pragma unroll
            for (int nh = 0; nh < 2; nh++) {
                const int oc = wn * 64 + j2 * 16 + nh * 8 + 2 * t4;
                const float bv0 = __ldg(bias + oc);
                const float bv1 = __ldg(bias + oc + 1);
                float* const p0 = rowp + (size_t)oc * HW2;
                float* const p1 = p0 + HW2;
                p0[g]     = acc[i][j2][nh][0] + bv0;
                p1[g]     = acc[i][j2][nh][1] + bv1;
                p0[g + 8] = acc[i][j2][nh][2] + bv0;
                p1[g + 8] = acc[i][j2][nh][3] + bv1;
            }
    }
}

extern "C" void kernel_launch(void* const* d_in, const int* in_sizes, int n_in,
                              void* d_out, int out_size)
{
    const float* x    = (const float*)d_in[0];
    const float* w    = (const float*)d_in[1];
    const float* bias = (const float*)d_in[2];
    float* out        = (float*)d_out;

    prep_xs<<<19152, 256>>>(x);                  // 3*16*64*114*14 / 256
    prep_wh<<<(KSZ * OUT_C) / 256, 256>>>(w);

    cudaFuncSetAttribute(conv_main,
                         cudaFuncAttributeMaxDynamicSharedMemorySize, SMEM_BYTES);
    conv_main<<<NB * 98, 256, SMEM_BYTES>>>(bias, out);
}

// round 8
// speedup vs baseline: 6.2311x; 1.1628x over previous
#include <cuda_runtime.h>
#include <cuda_fp16.h>
#include <cstdint>

// Conv2d 3x3 s1 p1, NCHW fp32 -> implicit GEMM, mma.sync.m16n8k16.f16 (f32 accum).
// K reordered k' = tap*64 + ic. Activations pre-converted to fp16 into 3 kw-shifted,
// h-padded copies (zero predication in mainloop, all-aligned 16B cp.async).
// R7: vectorized prep (one 10-float window -> all 3 copies) + SMEM-staged coalesced epilogue.

#define IN_C   64
#define OUT_C  128
#define HWD    112
#define NB     16
#define HW2    (HWD * HWD)          // 12544
#define KSZ    576
#define BK     32
#define NCHUNK 18
#define LDH    136                  // padded halves per k-row (272 B)
#define TILE_HB (BK * LDH * 2)      // 8704 B per A or B tile
#define STAGE_BYTES (2 * TILE_HB)   // 17408
#define NSTAGE 4
#define SMEM_BYTES (NSTAGE * STAGE_BYTES)   // 69632  (>= 128*132*4 = 67584 for epilogue)

#define XS_PLANE   (114 * 112)              // halves per (ic) plane
#define XS_COPY    (NB * IN_C * XS_PLANE)   // halves per kw copy
#define XS_TOTAL   (3 * XS_COPY)

__device__ __half g_xs[XS_TOTAL];        // [kw][n][ic][h'=114][w=112], zero borders
__device__ __half g_wh[KSZ * OUT_C];     // [k'][oc], k' = tap*64+ic

// ---------------- prep kernels ----------------
__global__ void __launch_bounds__(256)
prep_xs(const float* __restrict__ x) {
    const int idx = blockIdx.x * 256 + threadIdx.x;    // 16*64*114*14 = 1,634,304
    const int w8  = idx % 14;
    int r  = idx / 14;
    const int hp  = r % 114;  r /= 114;
    const int ic  = r & 63;   r >>= 6;
    const int n   = r;                                  // 0..15

    uint4 ov[3];
    const int h_in = hp - 1;
    if ((unsigned)h_in < HWD) {
        const float* xr = x + ((size_t)(n * IN_C + ic) * HWD + h_in) * HWD + w8 * 8;
        // window f(w0-1 .. w0+8) as halves hu[0..9], hu[i] = half(x[w0+i-1])
        float4 a = *reinterpret_cast<const float4*>(xr);
        float4 b = *reinterpret_cast<const float4*>(xr + 4);
        float fm1 = (w8 > 0)  ? __ldg(xr - 1) : 0.0f;
        float f8  = (w8 < 13) ? __ldg(xr + 8) : 0.0f;
        uint32_t hu[10];
        hu[0] = __half_as_ushort(__float2half_rn(fm1));
        hu[1] = __half_as_ushort(__float2half_rn(a.x));
        hu[2] = __half_as_ushort(__float2half_rn(a.y));
        hu[3] = __half_as_ushort(__float2half_rn(a.z));
        hu[4] = __half_as_ushort(__float2half_rn(a.w));
        hu[5] = __half_as_ushort(__float2half_rn(b.x));
        hu[6] = __half_as_ushort(__float2half_rn(b.y));
        hu[7] = __half_as_ushort(__float2half_rn(b.z));
        hu[8] = __half_as_ushort(__float2half_rn(b.w));
        hu[9] = __half_as_ushort(__float2half_rn(f8));
#pragma unroll
        for (int kw = 0; kw < 3; kw++) {    // out[j] = hu[j + kw]
            ov[kw].x = hu[kw + 0] | (hu[kw + 1] << 16);
            ov[kw].y = hu[kw + 2] | (hu[kw + 3] << 16);
            ov[kw].z = hu[kw + 4] | (hu[kw + 5] << 16);
            ov[kw].w = hu[kw + 6] | (hu[kw + 7] << 16);
        }
    } else {
        ov[0] = ov[1] = ov[2] = make_uint4(0, 0, 0, 0);
    }
#pragma unroll
    for (int kw = 0; kw < 3; kw++) {
        __half* dst = g_xs + ((size_t)(kw * NB + n) * IN_C + ic) * XS_PLANE
                           + hp * HWD + w8 * 8;
        *reinterpret_cast<uint4*>(dst) = ov[kw];
    }
}

__global__ void __launch_bounds__(256)
prep_wh(const float* __restrict__ w) {
    const int idx = blockIdx.x * 256 + threadIdx.x;    // 73728
    const int kp  = idx >> 7;
    const int oc  = idx & 127;
    const int tap = kp >> 6;
    const int ic  = kp & 63;
    g_wh[idx] = __float2half_rn(w[oc * KSZ + ic * 9 + tap]);
}

// ---------------- main kernel ----------------
__device__ __forceinline__ void mma_f16(float c[4], const uint32_t a[4],
                                        uint32_t b0, uint32_t b1) {
    asm volatile(
        "mma.sync.aligned.m16n8k16.row.col.f32.f16.f16.f32 "
        "{%0,%1,%2,%3}, {%4,%5,%6,%7}, {%8,%9}, {%0,%1,%2,%3};"
        : "+f"(c[0]), "+f"(c[1]), "+f"(c[2]), "+f"(c[3])
        : "r"(a[0]), "r"(a[1]), "r"(a[2]), "r"(a[3]), "r"(b0), "r"(b1));
}

#define LDSM_T(r0, r1, r2, r3, addr)                                          \
    asm volatile("ldmatrix.sync.aligned.m8n8.x4.trans.shared.b16 "            \
                 "{%0,%1,%2,%3}, [%4];"                                       \
                 : "=r"(r0), "=r"(r1), "=r"(r2), "=r"(r3) : "r"(addr))

__global__ void __launch_bounds__(256, 2)
conv_main(const float* __restrict__ bias, float* __restrict__ out)
{
    extern __shared__ __align__(16) char smc[];
    uint32_t sbase;
    asm("{ .reg .u64 t; cvta.to.shared.u64 t, %1; cvt.u32.u64 %0, t; }"
        : "=r"(sbase) : "l"(smc));

    const int tid  = threadIdx.x;
    const int wid  = tid >> 5;
    const int lane = tid & 31;

    const int b   = blockIdx.x;          // 1568 = 16 images * 98 tiles
    const int n   = b / 98;
    const int rem = b - n * 98;
    const int th  = rem / 7;
    const int tw  = rem - th * 7;
    const int h0  = th * 8;
    const int w0  = tw * 16;

    // ---- A-load constants (2 segments of 16B per thread) ----
    const char* const xsb = reinterpret_cast<const char*>(g_xs);
    long  srcA[2];
    uint32_t dstA[2];
#pragma unroll
    for (int s = 0; s < 2; s++) {
        const int seg  = tid + s * 256;        // 0..511
        const int ic   = seg >> 4;             // 0..31
        const int rr   = (seg >> 1) & 7;
        const int hf   = seg & 1;
        srcA[s] = ((long)(n * IN_C + ic) * 114 + h0 + rr) * 224 + w0 * 2 + hf * 16;
        dstA[s] = (uint32_t)(ic * LDH + rr * 16 + hf * 8) * 2;
    }
    // ---- B-load constants ----
    const char* const whb = reinterpret_cast<const char*>(g_wh);
    long  srcB[2];
    uint32_t dstB[2];
#pragma unroll
    for (int s = 0; s < 2; s++) {
        const int seg = tid + s * 256;
        const int kr  = seg >> 4;
        const int ocq = (seg & 15) * 8;
        srcB[s] = (long)(kr * OUT_C + ocq) * 2;
        dstB[s] = (uint32_t)(kr * LDH + ocq) * 2;
    }

    auto issue = [&](int t) {
        const int stage = t & 3;               // NSTAGE = 4
        const uint32_t abase = sbase + stage * STAGE_BYTES;
        const uint32_t bbase = abase + TILE_HB;
        const int tap = t >> 1;
        const int kh  = (tap >= 3) ? ((tap >= 6) ? 2 : 1) : 0;
        const int kw  = tap - kh * 3;
        const long aoff = (long)kw * (XS_COPY * 2)
                        + (long)((t & 1) * 32) * 25536   // ic0 * 114*224
                        + (long)kh * 224;
#pragma unroll
        for (int s = 0; s < 2; s++)
            asm volatile("cp.async.cg.shared.global [%0], [%1], 16;"
                         :: "r"(abase + dstA[s]), "l"(xsb + srcA[s] + aoff) : "memory");
        const long boff = (long)t * BK * OUT_C * 2;
#pragma unroll
        for (int s = 0; s < 2; s++)
            asm volatile("cp.async.cg.shared.global [%0], [%1], 16;"
                         :: "r"(bbase + dstB[s]), "l"(whb + srcB[s] + boff) : "memory");
    };

    // ---- microkernel coords ----
    const int wm = wid >> 1;     // px subtile of 32
    const int wn = wid & 1;      // oc subtile of 64
    const uint32_t aoffL = (uint32_t)(((lane >> 4) * 8 + (lane & 7)) * LDH
                                      + wm * 32 + ((lane >> 3) & 1) * 8);
    const uint32_t boffL = (uint32_t)(((((lane >> 3) & 1) * 8) + (lane & 7)) * LDH
                                      + wn * 64 + (lane >> 4) * 8);

    float acc[2][4][2][4];
#pragma unroll
    for (int i = 0; i < 2; i++)
#pragma unroll
        for (int j = 0; j < 4; j++)
#pragma unroll
            for (int h = 0; h < 2; h++)
#pragma unroll
                for (int c = 0; c < 4; c++) acc[i][j][h][c] = 0.0f;

    auto compute = [&](int stage) {
        const uint32_t abase = sbase + stage * STAGE_BYTES;
        const uint32_t bbase = abase + TILE_HB;
#pragma unroll
        for (int kk2 = 0; kk2 < 2; kk2++) {
            const uint32_t kof = kk2 * 16 * LDH;
            uint32_t a[2][4];
#pragma unroll
            for (int i = 0; i < 2; i++)
                LDSM_T(a[i][0], a[i][1], a[i][2], a[i][3],
                       abase + (aoffL + kof + i * 16) * 2);
#pragma unroll
            for (int j2 = 0; j2 < 4; j2++) {
                uint32_t b0, b1, b2, b3;
                LDSM_T(b0, b1, b2, b3, bbase + (boffL + kof + j2 * 16) * 2);
                mma_f16(acc[0][j2][0], a[0], b0, b1);
                mma_f16(acc[1][j2][0], a[1], b0, b1);
                mma_f16(acc[0][j2][1], a[0], b2, b3);
                mma_f16(acc[1][j2][1], a[1], b2, b3);
            }
        }
    };

    // ---- pipeline ----
    issue(0); asm volatile("cp.async.commit_group;" ::: "memory");
    issue(1); asm volatile("cp.async.commit_group;" ::: "memory");
    issue(2); asm volatile("cp.async.commit_group;" ::: "memory");

    for (int t = 0; t < NCHUNK; t++) {
        asm volatile("cp.async.wait_group 2;" ::: "memory");
        __syncthreads();
        compute(t & 3);
        if (t + 3 < NCHUNK) issue(t + 3);
        asm volatile("cp.async.commit_group;" ::: "memory");
    }

    // ---- epilogue: stage C in SMEM (stride 132 -> conflict-free), coalesced STG.128 ----
    __syncthreads();                      // pipeline SMEM is dead; reuse for C
    float* const Cs = reinterpret_cast<float*>(smc);
    const int g  = lane >> 2;
    const int t4 = lane & 3;

#pragma unroll
    for (int i = 0; i < 2; i++)
#pragma unroll
        for (int j2 = 0; j2 < 4; j2++)
#pragma unroll
            for (int nh = 0; nh < 2; nh++) {
                const int oc0 = wn * 64 + j2 * 16 + nh * 8 + 2 * t4;
                const int px0 = wm * 32 + i * 16 + g;
                Cs[oc0 * 132 + px0]             = acc[i][j2][nh][0];
                Cs[(oc0 + 1) * 132 + px0]       = acc[i][j2][nh][1];
                Cs[oc0 * 132 + px0 + 8]         = acc[i][j2][nh][2];
                Cs[(oc0 + 1) * 132 + px0 + 8]   = acc[i][j2][nh][3];
            }
    __syncthreads();

    float* const ob = out + (size_t)n * OUT_C * HW2 + h0 * HWD + w0;
#pragma unroll
    for (int r2 = 0; r2 < 16; r2++) {
        const int f   = tid + 256 * r2;       // (oc, h, w4)
        const int w4  = f & 3;
        const int hh2 = (f >> 2) & 7;
        const int oc  = f >> 5;
        float4 v = *reinterpret_cast<const float4*>(&Cs[oc * 132 + hh2 * 16 + w4 * 4]);
        const float bv = __ldg(bias + oc);
        v.x += bv; v.y += bv; v.z += bv; v.w += bv;
        *reinterpret_cast<float4*>(ob + (size_t)oc * HW2 + hh2 * HWD + w4 * 4) = v;
    }
}

extern "C" void kernel_launch(void* const* d_in, const int* in_sizes, int n_in,
                              void* d_out, int out_size)
{
    const float* x    = (const float*)d_in[0];
    const float* w    = (const float*)d_in[1];
    const float* bias = (const float*)d_in[2];
    float* out        = (float*)d_out;

    prep_xs<<<6384, 256>>>(x);                   // 16*64*114*14 / 256
    prep_wh<<<(KSZ * OUT_C) / 256, 256>>>(w);

    cudaFuncSetAttribute(conv_main,
                         cudaFuncAttributeMaxDynamicSharedMemorySize, SMEM_BYTES);
    conv_main<<<NB * 98, 256, SMEM_BYTES>>>(bias, out);
}